// round 8
// baseline (speedup 1.0000x reference)
#include <cuda_runtime.h>
#include <cuda_fp16.h>
#include <cstdint>

#define BB 16
#define NN 2048
#define DD 128

// scratch
__device__ float g_q[BB * NN];
__device__ float g_k[BB * NN];
__device__ float g_ek[BB * NN];
__device__ float g_ek2[BB * NN];
__device__ float g_part[8][BB * NN];
__device__ float4 g_jpk[BB * NN];           // (q, e^q*rden, e^.01q*rden, rden)
__device__ uint32_t g_bits[NN * (NN / 32)]; // adj bitmask, word = i*64 + j/32
// seq_fts^T single fp16, chunk-contiguous: [b][j/32][d][j%32]
__device__ __half g_F[(size_t)BB * DD * NN];

// ---------------------------------------------------------------------------
// helpers
// ---------------------------------------------------------------------------
__device__ __forceinline__ uint32_t smem_u32(const void* p) {
    uint32_t a;
    asm("{ .reg .u64 t; cvta.to.shared.u64 t, %1; cvt.u32.u64 %0, t; }" : "=r"(a) : "l"(p));
    return a;
}
__device__ __forceinline__ void cpa16(uint32_t dst, const void* src) {
    asm volatile("cp.async.cg.shared.global [%0], [%1], 16;" :: "r"(dst), "l"(src));
}
#define CP_COMMIT() asm volatile("cp.async.commit_group;")
#define CP_WAIT0()  asm volatile("cp.async.wait_group 0;" ::: "memory")

// pitch: 40 f16 = 80 bytes per 32-elem row (conflict-free for ldmatrix)
#define PITCHB 80
#define TILEB  (128 * PITCHB)   // 10240 bytes (128-row operand)
#define ASZ    (64 * PITCHB)    // 5120 bytes (64-row A operand)
#define STAGE  (ASZ + TILEB)    // A + B = 15360

__device__ __forceinline__ void ldmA4(uint32_t base, int lane, uint32_t* a) {
    uint32_t addr = base + (uint32_t)((lane & 15) * PITCHB) + (uint32_t)(((lane >> 4) & 1) << 4);
    asm volatile("ldmatrix.sync.aligned.m8n8.x4.shared.b16 {%0,%1,%2,%3}, [%4];"
                 : "=r"(a[0]), "=r"(a[1]), "=r"(a[2]), "=r"(a[3]) : "r"(addr));
}
__device__ __forceinline__ void ldmB4(uint32_t base, int lane, uint32_t* r) {
    uint32_t addr = base + (uint32_t)(((lane & 7) + ((lane >> 4) << 3)) * PITCHB)
                         + (uint32_t)(((lane >> 3) & 1) << 4);
    asm volatile("ldmatrix.sync.aligned.m8n8.x4.shared.b16 {%0,%1,%2,%3}, [%4];"
                 : "=r"(r[0]), "=r"(r[1]), "=r"(r[2]), "=r"(r[3]) : "r"(addr));
}
__device__ __forceinline__ void mma16816h(float* d, const uint32_t* a, uint32_t b0, uint32_t b1) {
    asm volatile(
        "mma.sync.aligned.m16n8k16.row.col.f32.f16.f16.f32 "
        "{%0,%1,%2,%3}, {%4,%5,%6,%7}, {%8,%9}, {%0,%1,%2,%3};"
        : "+f"(d[0]), "+f"(d[1]), "+f"(d[2]), "+f"(d[3])
        : "r"(a[0]), "r"(a[1]), "r"(a[2]), "r"(a[3]), "r"(b0), "r"(b1));
}

__device__ __forceinline__ void split2h(float v0, float v1, uint32_t& hw, uint32_t& lw) {
    __half h0 = __float2half_rn(v0);
    __half h1 = __float2half_rn(v1);
    __half2 hh; hh.x = h0; hh.y = h1;
    __half2 ll;
    ll.x = __float2half_rn(v0 - __half2float(h0));
    ll.y = __float2half_rn(v1 - __half2float(h1));
    hw = *(uint32_t*)&hh;
    lw = *(uint32_t*)&ll;
}
__device__ __forceinline__ uint32_t pack2h(float v0, float v1) {
    __half2 hh; hh.x = __float2half_rn(v0); hh.y = __float2half_rn(v1);
    return *(uint32_t*)&hh;
}

// 3-term split mainloop (k_emb)
template <int NIT>
__device__ __forceinline__ void mma_chunk3(float (*acc)[4],
                                           uint32_t sAH, uint32_t sAL,
                                           uint32_t sBH, uint32_t sBL,
                                           int wr, int wc, int lane) {
    #pragma unroll
    for (int ks = 0; ks < 2; ks++) {
        uint32_t bh[8], bl[8];
        #pragma unroll
        for (int ntp = 0; ntp < 2; ntp++) {
            uint32_t boff = (uint32_t)((wc * 32 + ntp * 16) * PITCHB + ks * 32);
            ldmB4(sBH + boff, lane, bh + ntp * 4);
            ldmB4(sBL + boff, lane, bl + ntp * 4);
        }
        #pragma unroll
        for (int it = 0; it < NIT; it++) {
            uint32_t aoff = (uint32_t)(((wr * NIT + it) * 16) * PITCHB + ks * 32);
            uint32_t ah[4], al[4];
            ldmA4(sAH + aoff, lane, ah);
            ldmA4(sAL + aoff, lane, al);
            #pragma unroll
            for (int nt = 0; nt < 4; nt++) {
                mma16816h(acc[it * 4 + nt], ah, bh[nt * 2], bh[nt * 2 + 1]);
                mma16816h(acc[it * 4 + nt], ah, bl[nt * 2], bl[nt * 2 + 1]);
                mma16816h(acc[it * 4 + nt], al, bh[nt * 2], bh[nt * 2 + 1]);
            }
        }
    }
}

// single-term mainloop (k_attn)
template <int NIT>
__device__ __forceinline__ void mma_chunk1(float (*acc)[4],
                                           uint32_t sA, uint32_t sB,
                                           int wr, int wc, int lane) {
    #pragma unroll
    for (int ks = 0; ks < 2; ks++) {
        uint32_t bf[8];
        #pragma unroll
        for (int ntp = 0; ntp < 2; ntp++) {
            uint32_t boff = (uint32_t)((wc * 32 + ntp * 16) * PITCHB + ks * 32);
            ldmB4(sB + boff, lane, bf + ntp * 4);
        }
        #pragma unroll
        for (int it = 0; it < NIT; it++) {
            uint32_t aoff = (uint32_t)(((wr * NIT + it) * 16) * PITCHB + ks * 32);
            uint32_t ah[4];
            ldmA4(sA + aoff, lane, ah);
            #pragma unroll
            for (int nt = 0; nt < 4; nt++)
                mma16816h(acc[it * 4 + nt], ah, bf[nt * 2], bf[nt * 2 + 1]);
        }
    }
}

// ---------------------------------------------------------------------------
// Kernel 0: pack adj into bitmask (one-time; adj is exactly {0,1})
// ---------------------------------------------------------------------------
__global__ __launch_bounds__(256) void k_prep(const float* __restrict__ adj)
{
    const int lane = threadIdx.x & 31;
    const int wg   = blockIdx.x * 8 + (threadIdx.x >> 5);   // 0..4095
    uint32_t keep = 0;
    #pragma unroll
    for (int t = 0; t < 32; t++) {
        size_t fidx = ((size_t)wg * 32 + t) * 32 + lane;
        float v = adj[fidx];
        uint32_t m = __ballot_sync(0xffffffffu, v != 0.f);
        if (lane == t) keep = m;
    }
    g_bits[(size_t)wg * 32 + lane] = keep;
}

// ---------------------------------------------------------------------------
// Kernel 1: seq_fts = x @ W^T + b_emb via fp16-split mma.sync.
// ---------------------------------------------------------------------------
__global__ __launch_bounds__(256) void k_emb(
    const float* __restrict__ x, const float* __restrict__ W,
    const float* __restrict__ b_emb,
    const float* __restrict__ w_q, const float* __restrict__ b_q,
    const float* __restrict__ w_k, const float* __restrict__ b_k)
{
    __shared__ __align__(16) uint8_t sm[4 * TILEB];
    __shared__ float qred[128], kred[128];

    const int tid  = threadIdx.x;
    const int lane = tid & 31;
    const int wid  = tid >> 5;
    const int wr   = wid >> 2;
    const int wc   = wid & 3;
    const int blk  = blockIdx.x;
    const size_t row0 = (size_t)blk * 128;

    if (tid < 128) { qred[tid] = 0.f; kred[tid] = 0.f; }

    const uint32_t sb  = smem_u32(sm);
    const uint32_t sAH = sb, sAL = sb + TILEB, sBH = sb + 2 * TILEB, sBL = sb + 3 * TILEB;

    float acc[16][4];
    #pragma unroll
    for (int i = 0; i < 16; i++)
        #pragma unroll
        for (int j = 0; j < 4; j++) acc[i][j] = 0.f;

    const int jj = (tid & 15) * 2;
    const int rb = tid >> 4;

    for (int k0 = 0; k0 < DD; k0 += 32) {
        __syncthreads();
        #pragma unroll
        for (int g = 0; g < 8; g++) {
            int r = rb + g * 16;
            float2 xv = *(const float2*)(x + (row0 + r) * DD + k0 + jj);
            float2 wv = *(const float2*)(W + (size_t)r * DD + k0 + jj);
            uint32_t hw, lw;
            split2h(xv.x, xv.y, hw, lw);
            *(uint32_t*)(sm + (size_t)0 * TILEB + r * PITCHB + jj * 2) = hw;
            *(uint32_t*)(sm + (size_t)1 * TILEB + r * PITCHB + jj * 2) = lw;
            split2h(wv.x, wv.y, hw, lw);
            *(uint32_t*)(sm + (size_t)2 * TILEB + r * PITCHB + jj * 2) = hw;
            *(uint32_t*)(sm + (size_t)3 * TILEB + r * PITCHB + jj * 2) = lw;
        }
        __syncthreads();
        mma_chunk3<4>(acc, sAH, sAL, sBH, sBL, wr, wc, lane);
    }

    float2 be[4], wq2[4], wk2[4];
    #pragma unroll
    for (int nt = 0; nt < 4; nt++) {
        int c = wc * 32 + nt * 8 + (lane & 3) * 2;
        be[nt]  = *(const float2*)(b_emb + c);
        wq2[nt] = *(const float2*)(w_q + c);
        wk2[nt] = *(const float2*)(w_k + c);
    }
    __syncthreads();

    #pragma unroll
    for (int it = 0; it < 4; it++) {
        float q0 = 0.f, q8 = 0.f, kk0 = 0.f, kk8 = 0.f;
        #pragma unroll
        for (int nt = 0; nt < 4; nt++) {
            float* a = acc[it * 4 + nt];
            a[0] += be[nt].x; a[1] += be[nt].y;
            a[2] += be[nt].x; a[3] += be[nt].y;
            q0 += a[0] * wq2[nt].x + a[1] * wq2[nt].y;
            q8 += a[2] * wq2[nt].x + a[3] * wq2[nt].y;
            kk0 += a[0] * wk2[nt].x + a[1] * wk2[nt].y;
            kk8 += a[2] * wk2[nt].x + a[3] * wk2[nt].y;
        }
        #pragma unroll
        for (int off = 1; off <= 2; off <<= 1) {
            q0 += __shfl_xor_sync(0xffffffffu, q0, off);
            q8 += __shfl_xor_sync(0xffffffffu, q8, off);
            kk0 += __shfl_xor_sync(0xffffffffu, kk0, off);
            kk8 += __shfl_xor_sync(0xffffffffu, kk8, off);
        }
        if ((lane & 3) == 0) {
            int r = wr * 64 + it * 16 + (lane >> 2);
            atomicAdd(&qred[r], q0);
            atomicAdd(&qred[r + 8], q8);
            atomicAdd(&kred[r], kk0);
            atomicAdd(&kred[r + 8], kk8);
        }
    }

    // transpose + store single fp16
    __half* T = (__half*)sm;
    const int b64 = (blk >> 4) * 64;
    const int jc0 = (blk & 15) * 4;

    __syncthreads();
    #pragma unroll
    for (int it = 0; it < 4; it++) {
        int r = wr * 64 + it * 16 + (lane >> 2);
        #pragma unroll
        for (int nt = 0; nt < 4; nt++) {
            int c = wc * 32 + nt * 8 + (lane & 3) * 2;
            float* a = acc[it * 4 + nt];
            #pragma unroll
            for (int u = 0; u < 4; u++)
                T[(c + (u & 1)) * 136 + r + (u >> 1) * 8] = __float2half_rn(a[u]);
        }
    }
    __syncthreads();
    #pragma unroll
    for (int g = 0; g < 8; g++) {
        int lin = tid + g * 256;
        int d   = lin >> 4;
        int seg = lin & 15;
        uint4 v = *(const uint4*)((const uint8_t*)T + d * 272 + seg * 16);
        size_t dst = (((size_t)(b64 + jc0 + (seg >> 2)) * 128 + d) * 32) + (seg & 3) * 8;
        *(uint4*)(g_F + dst) = v;
    }

    __syncthreads();
    if (tid < 128) {
        g_q[row0 + tid] = qred[tid] + b_q[0];
        g_k[row0 + tid] = kred[tid] + b_k[0];
    }
}

// ---------------------------------------------------------------------------
// Kernel 1b: e^k, e^0.01k per (b, i)
// ---------------------------------------------------------------------------
__global__ __launch_bounds__(256) void k_ek()
{
    const int idx = blockIdx.x * 256 + threadIdx.x;
    float kk = g_k[idx];
    g_ek[idx]  = __expf(kk);
    g_ek2[idx] = __expf(0.01f * kk);
}

// ---------------------------------------------------------------------------
// Kernel 2a: partial column sums via bitmask + factored exp (no MUFU in loop)
// ---------------------------------------------------------------------------
__global__ __launch_bounds__(128) void k_denom()
{
    __shared__ float sk[256], se1[256], se2[256];
    __shared__ uint32_t sbt[1024];

    const int tid = threadIdx.x;
    const int j   = blockIdx.x * 128 + tid;
    const int b   = blockIdx.y;
    const int i0  = blockIdx.z * 256;
    const int jw  = blockIdx.x * 4;

    for (int s = tid; s < 256; s += 128) {
        sk[s]  = g_k[b * NN + i0 + s];
        se1[s] = g_ek[b * NN + i0 + s];
        se2[s] = g_ek2[b * NN + i0 + s];
    }
    for (int s = tid; s < 1024; s += 128)
        sbt[s] = g_bits[(size_t)(i0 + (s >> 2)) * 64 + jw + (s & 3)];
    __syncthreads();

    const float q   = g_q[b * NN + j];
    const float eq  = __expf(q);
    const float eq2 = __expf(0.01f * q);
    const int wsel = tid >> 5;
    const int bsh  = tid & 31;

    float t1 = 0.f, t2 = 0.f;
    int nb = 0;
    #pragma unroll 4
    for (int i = 0; i < 256; i++) {
        uint32_t bit = (sbt[i * 4 + wsel] >> bsh) & 1u;
        float z = sk[i] + q;
        bool pos = z > 0.f;
        if (bit) {
            if (pos) t1 += se1[i]; else t2 += se2[i];
        }
        nb += (int)bit;
    }
    g_part[blockIdx.z][b * NN + j] = eq * t1 + eq2 * t2 + (float)(256 - nb);
}

// Kernel 2b: reduce partials -> rden + per-column pack (q, e^q*r, e^.01q*r, r)
__global__ __launch_bounds__(256) void k_rcp()
{
    const int idx = blockIdx.x * 256 + threadIdx.x;
    float s = 0.f;
    #pragma unroll
    for (int p = 0; p < 8; p++) s += g_part[p][idx];
    float r = __frcp_rn(s);
    float q = g_q[idx];
    g_jpk[idx] = make_float4(q, __expf(q) * r, __expf(0.01f * q) * r, r);
}

// ---------------------------------------------------------------------------
// Kernel 3: pipelined attention GEMM, fp16 operands, bitmask P-staging,
// cp.async B. Tile 64i x 128d, j-chunk 32, double-buffered.
// ---------------------------------------------------------------------------
__global__ __launch_bounds__(256, 2) void k_attn(float* __restrict__ out)
{
    __shared__ __align__(16) uint8_t smd[2 * STAGE];

    const int tid  = threadIdx.x;
    const int lane = tid & 31;
    const int wid  = tid >> 5;
    const int wr   = wid >> 2;
    const int wc   = wid & 3;
    const int b    = blockIdx.y;
    const int i0   = blockIdx.x * 64;

    const uint32_t sb = smem_u32(smd);

    const float4* __restrict__ jp = g_jpk + b * NN;
    const __half* __restrict__ Fb = g_F + (size_t)b * DD * NN;

    float acc[8][4];
    #pragma unroll
    for (int i = 0; i < 8; i++)
        #pragma unroll
        for (int j = 0; j < 4; j++) acc[i][j] = 0.f;

    const int jj = (tid & 15) * 2;
    const int ib = tid >> 4;

    float kv[4], ekv[4], ek2v[4];
    #pragma unroll
    for (int g = 0; g < 4; g++) {
        int i = i0 + ib + g * 16;
        kv[g]   = g_k[b * NN + i];
        ekv[g]  = g_ek[b * NN + i];
        ek2v[g] = g_ek2[b * NN + i];
    }

    // ---- prologue: stage chunk 0 ----
    {
        #pragma unroll
        for (int g = 0; g < 2; g++) {
            int idx = tid + g * 256;
            int d = idx >> 2, seg = idx & 3;
            cpa16(sb + ASZ + (uint32_t)(d * PITCHB + seg * 16),
                  (const uint8_t*)Fb + idx * 16);
        }
        CP_COMMIT();
        float4 j0p = jp[jj], j1p = jp[jj + 1];
        #pragma unroll
        for (int g = 0; g < 4; g++) {
            int i = ib + g * 16;
            uint32_t w = g_bits[(size_t)(i0 + i) * 64];
            float z0 = kv[g] + j0p.x;
            float m0 = (z0 > 0.f) ? ekv[g] * j0p.y : ek2v[g] * j0p.z;
            float p0 = ((w >> jj) & 1u) ? m0 : j0p.w;
            float z1 = kv[g] + j1p.x;
            float m1 = (z1 > 0.f) ? ekv[g] * j1p.y : ek2v[g] * j1p.z;
            float p1 = ((w >> (jj + 1)) & 1u) ? m1 : j1p.w;
            *(uint32_t*)(smd + i * PITCHB + jj * 2) = pack2h(p0, p1);
        }
        CP_WAIT0();
        __syncthreads();
    }

    for (int c = 0; c < 64; c++) {
        const uint32_t cur = sb + (uint32_t)((c & 1) * STAGE);
        const uint32_t nxo = (uint32_t)(((c + 1) & 1) * STAGE);
        const bool pf = (c < 63);
        const int j0n = (c + 1) * 32;

        float4 j0p, j1p;
        uint32_t bw[4];
        if (pf) {
            const uint8_t* fsrc = (const uint8_t*)(Fb + (size_t)(j0n >> 5) * 4096);
            #pragma unroll
            for (int g = 0; g < 2; g++) {
                int idx = tid + g * 256;
                int d = idx >> 2, seg = idx & 3;
                cpa16(sb + nxo + ASZ + (uint32_t)(d * PITCHB + seg * 16), fsrc + idx * 16);
            }
            CP_COMMIT();
            j0p = jp[j0n + jj];
            j1p = jp[j0n + jj + 1];
            #pragma unroll
            for (int g = 0; g < 4; g++)
                bw[g] = g_bits[(size_t)(i0 + ib + g * 16) * 64 + (j0n >> 5)];
        }

        // MMA on current stage
        mma_chunk1<2>(acc, cur, cur + ASZ, wr, wc, lane);

        // compute + store next A
        if (pf) {
            #pragma unroll
            for (int g = 0; g < 4; g++) {
                int i = ib + g * 16;
                float z0 = kv[g] + j0p.x;
                float m0 = (z0 > 0.f) ? ekv[g] * j0p.y : ek2v[g] * j0p.z;
                float p0 = ((bw[g] >> jj) & 1u) ? m0 : j0p.w;
                float z1 = kv[g] + j1p.x;
                float m1 = (z1 > 0.f) ? ekv[g] * j1p.y : ek2v[g] * j1p.z;
                float p1 = ((bw[g] >> (jj + 1)) & 1u) ? m1 : j1p.w;
                *(uint32_t*)(smd + nxo + i * PITCHB + jj * 2) = pack2h(p0, p1);
            }
            CP_WAIT0();
        }
        __syncthreads();
    }

    // epilogue
    #pragma unroll
    for (int it = 0; it < 2; it++) {
        int r = i0 + wr * 32 + it * 16 + (lane >> 2);
        #pragma unroll
        for (int nt = 0; nt < 4; nt++) {
            int c = wc * 32 + nt * 8 + (lane & 3) * 2;
            float* a = acc[it * 4 + nt];
            *(float2*)(out + ((size_t)b * NN + r) * DD + c)     = make_float2(a[0], a[1]);
            *(float2*)(out + ((size_t)b * NN + r + 8) * DD + c) = make_float2(a[2], a[3]);
        }
    }
}

// ---------------------------------------------------------------------------
extern "C" void kernel_launch(void* const* d_in, const int* in_sizes, int n_in,
                              void* d_out, int out_size)
{
    (void)in_sizes; (void)n_in; (void)out_size;
    const float* x     = (const float*)d_in[0];
    const float* adj   = (const float*)d_in[1];
    const float* W_emb = (const float*)d_in[2];
    const float* b_emb = (const float*)d_in[3];
    const float* w_q   = (const float*)d_in[4];
    const float* b_q   = (const float*)d_in[5];
    const float* w_k   = (const float*)d_in[6];
    const float* b_k   = (const float*)d_in[7];
    float* out = (float*)d_out;

    k_prep<<<512, 256>>>(adj);
    k_emb<<<(BB * NN) / 128, 256>>>(x, W_emb, b_emb, w_q, b_q, w_k, b_k);
    k_ek<<<(BB * NN) / 256, 256>>>();
    k_denom<<<dim3(NN / 128, BB, 8), 128>>>();
    k_rcp<<<(BB * NN) / 256, 256>>>();
    k_attn<<<dim3(NN / 64, BB), 256>>>(out);
}

// round 9
// speedup vs baseline: 1.0466x; 1.0466x over previous
#include <cuda_runtime.h>
#include <cuda_fp16.h>
#include <cstdint>

#define BB 16
#define NN 2048
#define DD 128

// scratch
__device__ float g_q[BB * NN];
__device__ float g_k[BB * NN];
__device__ float g_ek[BB * NN];
__device__ float g_ek2[BB * NN];
__device__ float4 g_kpk[BB * NN];           // (k, e^k, e^.01k, 0)
__device__ float g_part[8][BB * NN];
__device__ float4 g_jpk[BB * NN];           // (q, e^q*rden, e^.01q*rden, rden)
__device__ uint32_t g_bits[NN * (NN / 32)];   // bits along j: word = i*64 + j/32
__device__ uint32_t g_bitsT[(NN / 32) * NN];  // bits along i: word = (i/32)*NN + j
// seq_fts^T single fp16, chunk-contiguous: [b][j/32][d][j%32]
__device__ __half g_F[(size_t)BB * DD * NN];

// ---------------------------------------------------------------------------
// helpers
// ---------------------------------------------------------------------------
__device__ __forceinline__ uint32_t smem_u32(const void* p) {
    uint32_t a;
    asm("{ .reg .u64 t; cvta.to.shared.u64 t, %1; cvt.u32.u64 %0, t; }" : "=r"(a) : "l"(p));
    return a;
}
__device__ __forceinline__ void cpa16(uint32_t dst, const void* src) {
    asm volatile("cp.async.cg.shared.global [%0], [%1], 16;" :: "r"(dst), "l"(src));
}
#define CP_COMMIT() asm volatile("cp.async.commit_group;")
#define CP_WAIT0()  asm volatile("cp.async.wait_group 0;" ::: "memory")

// pitch: 40 f16 = 80 bytes per 32-elem row (conflict-free for ldmatrix)
#define PITCHB 80
#define TILEB  (128 * PITCHB)   // 10240 bytes (128-row operand)
#define ASZ    (64 * PITCHB)    // 5120 bytes (64-row A operand)
#define STAGE  (ASZ + TILEB)    // A + B = 15360

__device__ __forceinline__ void ldmA4(uint32_t base, int lane, uint32_t* a) {
    uint32_t addr = base + (uint32_t)((lane & 15) * PITCHB) + (uint32_t)(((lane >> 4) & 1) << 4);
    asm volatile("ldmatrix.sync.aligned.m8n8.x4.shared.b16 {%0,%1,%2,%3}, [%4];"
                 : "=r"(a[0]), "=r"(a[1]), "=r"(a[2]), "=r"(a[3]) : "r"(addr));
}
__device__ __forceinline__ void ldmB4(uint32_t base, int lane, uint32_t* r) {
    uint32_t addr = base + (uint32_t)(((lane & 7) + ((lane >> 4) << 3)) * PITCHB)
                         + (uint32_t)(((lane >> 3) & 1) << 4);
    asm volatile("ldmatrix.sync.aligned.m8n8.x4.shared.b16 {%0,%1,%2,%3}, [%4];"
                 : "=r"(r[0]), "=r"(r[1]), "=r"(r[2]), "=r"(r[3]) : "r"(addr));
}
__device__ __forceinline__ void mma16816h(float* d, const uint32_t* a, uint32_t b0, uint32_t b1) {
    asm volatile(
        "mma.sync.aligned.m16n8k16.row.col.f32.f16.f16.f32 "
        "{%0,%1,%2,%3}, {%4,%5,%6,%7}, {%8,%9}, {%0,%1,%2,%3};"
        : "+f"(d[0]), "+f"(d[1]), "+f"(d[2]), "+f"(d[3])
        : "r"(a[0]), "r"(a[1]), "r"(a[2]), "r"(a[3]), "r"(b0), "r"(b1));
}

__device__ __forceinline__ void split2h(float v0, float v1, uint32_t& hw, uint32_t& lw) {
    __half h0 = __float2half_rn(v0);
    __half h1 = __float2half_rn(v1);
    __half2 hh; hh.x = h0; hh.y = h1;
    __half2 ll;
    ll.x = __float2half_rn(v0 - __half2float(h0));
    ll.y = __float2half_rn(v1 - __half2float(h1));
    hw = *(uint32_t*)&hh;
    lw = *(uint32_t*)&ll;
}
__device__ __forceinline__ uint32_t pack2h(float v0, float v1) {
    __half2 hh; hh.x = __float2half_rn(v0); hh.y = __float2half_rn(v1);
    return *(uint32_t*)&hh;
}

// 3-term split mainloop (k_emb)
template <int NIT>
__device__ __forceinline__ void mma_chunk3(float (*acc)[4],
                                           uint32_t sAH, uint32_t sAL,
                                           uint32_t sBH, uint32_t sBL,
                                           int wr, int wc, int lane) {
    #pragma unroll
    for (int ks = 0; ks < 2; ks++) {
        uint32_t bh[8], bl[8];
        #pragma unroll
        for (int ntp = 0; ntp < 2; ntp++) {
            uint32_t boff = (uint32_t)((wc * 32 + ntp * 16) * PITCHB + ks * 32);
            ldmB4(sBH + boff, lane, bh + ntp * 4);
            ldmB4(sBL + boff, lane, bl + ntp * 4);
        }
        #pragma unroll
        for (int it = 0; it < NIT; it++) {
            uint32_t aoff = (uint32_t)(((wr * NIT + it) * 16) * PITCHB + ks * 32);
            uint32_t ah[4], al[4];
            ldmA4(sAH + aoff, lane, ah);
            ldmA4(sAL + aoff, lane, al);
            #pragma unroll
            for (int nt = 0; nt < 4; nt++) {
                mma16816h(acc[it * 4 + nt], ah, bh[nt * 2], bh[nt * 2 + 1]);
                mma16816h(acc[it * 4 + nt], ah, bl[nt * 2], bl[nt * 2 + 1]);
                mma16816h(acc[it * 4 + nt], al, bh[nt * 2], bh[nt * 2 + 1]);
            }
        }
    }
}

// single-term mainloop (k_attn)
template <int NIT>
__device__ __forceinline__ void mma_chunk1(float (*acc)[4],
                                           uint32_t sA, uint32_t sB,
                                           int wr, int wc, int lane) {
    #pragma unroll
    for (int ks = 0; ks < 2; ks++) {
        uint32_t bf[8];
        #pragma unroll
        for (int ntp = 0; ntp < 2; ntp++) {
            uint32_t boff = (uint32_t)((wc * 32 + ntp * 16) * PITCHB + ks * 32);
            ldmB4(sB + boff, lane, bf + ntp * 4);
        }
        #pragma unroll
        for (int it = 0; it < NIT; it++) {
            uint32_t aoff = (uint32_t)(((wr * NIT + it) * 16) * PITCHB + ks * 32);
            uint32_t ah[4];
            ldmA4(sA + aoff, lane, ah);
            #pragma unroll
            for (int nt = 0; nt < 4; nt++)
                mma16816h(acc[it * 4 + nt], ah, bf[nt * 2], bf[nt * 2 + 1]);
        }
    }
}

// ---------------------------------------------------------------------------
// Kernel 0a: pack adj into bitmask (adj is exactly {0,1})
// ---------------------------------------------------------------------------
__global__ __launch_bounds__(256) void k_prep(const float* __restrict__ adj)
{
    const int lane = threadIdx.x & 31;
    const int wg   = blockIdx.x * 8 + (threadIdx.x >> 5);   // 0..4095
    uint32_t keep = 0;
    #pragma unroll
    for (int t = 0; t < 32; t++) {
        size_t fidx = ((size_t)wg * 32 + t) * 32 + lane;
        float v = adj[fidx];
        uint32_t m = __ballot_sync(0xffffffffu, v != 0.f);
        if (lane == t) keep = m;
    }
    g_bits[(size_t)wg * 32 + lane] = keep;
}

// Kernel 0b: bit-transpose g_bits -> g_bitsT (bits along i, j-major words)
__global__ __launch_bounds__(256) void k_prepT()
{
    const int lane = threadIdx.x & 31;
    const int wg   = blockIdx.x * 8 + (threadIdx.x >> 5);   // 0..4095
    const int ic   = wg >> 6;      // i-chunk (0..63)
    const int jw   = wg & 63;      // source word column (0..63)
    uint32_t w = g_bits[(size_t)(ic * 32 + lane) * 64 + jw];
    uint32_t keep = 0;
    #pragma unroll
    for (int t = 0; t < 32; t++) {
        uint32_t m = __ballot_sync(0xffffffffu, (w >> t) & 1u);
        if (lane == t) keep = m;
    }
    g_bitsT[(size_t)ic * NN + jw * 32 + lane] = keep;
}

// ---------------------------------------------------------------------------
// Kernel 1: seq_fts = x @ W^T + b_emb via fp16-split mma.sync.
// ---------------------------------------------------------------------------
__global__ __launch_bounds__(256) void k_emb(
    const float* __restrict__ x, const float* __restrict__ W,
    const float* __restrict__ b_emb,
    const float* __restrict__ w_q, const float* __restrict__ b_q,
    const float* __restrict__ w_k, const float* __restrict__ b_k)
{
    __shared__ __align__(16) uint8_t sm[4 * TILEB];
    __shared__ float qred[128], kred[128];

    const int tid  = threadIdx.x;
    const int lane = tid & 31;
    const int wid  = tid >> 5;
    const int wr   = wid >> 2;
    const int wc   = wid & 3;
    const int blk  = blockIdx.x;
    const size_t row0 = (size_t)blk * 128;

    if (tid < 128) { qred[tid] = 0.f; kred[tid] = 0.f; }

    const uint32_t sb  = smem_u32(sm);
    const uint32_t sAH = sb, sAL = sb + TILEB, sBH = sb + 2 * TILEB, sBL = sb + 3 * TILEB;

    float acc[16][4];
    #pragma unroll
    for (int i = 0; i < 16; i++)
        #pragma unroll
        for (int j = 0; j < 4; j++) acc[i][j] = 0.f;

    const int jj = (tid & 15) * 2;
    const int rb = tid >> 4;

    for (int k0 = 0; k0 < DD; k0 += 32) {
        __syncthreads();
        #pragma unroll
        for (int g = 0; g < 8; g++) {
            int r = rb + g * 16;
            float2 xv = *(const float2*)(x + (row0 + r) * DD + k0 + jj);
            float2 wv = *(const float2*)(W + (size_t)r * DD + k0 + jj);
            uint32_t hw, lw;
            split2h(xv.x, xv.y, hw, lw);
            *(uint32_t*)(sm + (size_t)0 * TILEB + r * PITCHB + jj * 2) = hw;
            *(uint32_t*)(sm + (size_t)1 * TILEB + r * PITCHB + jj * 2) = lw;
            split2h(wv.x, wv.y, hw, lw);
            *(uint32_t*)(sm + (size_t)2 * TILEB + r * PITCHB + jj * 2) = hw;
            *(uint32_t*)(sm + (size_t)3 * TILEB + r * PITCHB + jj * 2) = lw;
        }
        __syncthreads();
        mma_chunk3<4>(acc, sAH, sAL, sBH, sBL, wr, wc, lane);
    }

    float2 be[4], wq2[4], wk2[4];
    #pragma unroll
    for (int nt = 0; nt < 4; nt++) {
        int c = wc * 32 + nt * 8 + (lane & 3) * 2;
        be[nt]  = *(const float2*)(b_emb + c);
        wq2[nt] = *(const float2*)(w_q + c);
        wk2[nt] = *(const float2*)(w_k + c);
    }
    __syncthreads();

    #pragma unroll
    for (int it = 0; it < 4; it++) {
        float q0 = 0.f, q8 = 0.f, kk0 = 0.f, kk8 = 0.f;
        #pragma unroll
        for (int nt = 0; nt < 4; nt++) {
            float* a = acc[it * 4 + nt];
            a[0] += be[nt].x; a[1] += be[nt].y;
            a[2] += be[nt].x; a[3] += be[nt].y;
            q0 += a[0] * wq2[nt].x + a[1] * wq2[nt].y;
            q8 += a[2] * wq2[nt].x + a[3] * wq2[nt].y;
            kk0 += a[0] * wk2[nt].x + a[1] * wk2[nt].y;
            kk8 += a[2] * wk2[nt].x + a[3] * wk2[nt].y;
        }
        #pragma unroll
        for (int off = 1; off <= 2; off <<= 1) {
            q0 += __shfl_xor_sync(0xffffffffu, q0, off);
            q8 += __shfl_xor_sync(0xffffffffu, q8, off);
            kk0 += __shfl_xor_sync(0xffffffffu, kk0, off);
            kk8 += __shfl_xor_sync(0xffffffffu, kk8, off);
        }
        if ((lane & 3) == 0) {
            int r = wr * 64 + it * 16 + (lane >> 2);
            atomicAdd(&qred[r], q0);
            atomicAdd(&qred[r + 8], q8);
            atomicAdd(&kred[r], kk0);
            atomicAdd(&kred[r + 8], kk8);
        }
    }

    // transpose + store single fp16
    __half* T = (__half*)sm;
    const int b64 = (blk >> 4) * 64;
    const int jc0 = (blk & 15) * 4;

    __syncthreads();
    #pragma unroll
    for (int it = 0; it < 4; it++) {
        int r = wr * 64 + it * 16 + (lane >> 2);
        #pragma unroll
        for (int nt = 0; nt < 4; nt++) {
            int c = wc * 32 + nt * 8 + (lane & 3) * 2;
            float* a = acc[it * 4 + nt];
            #pragma unroll
            for (int u = 0; u < 4; u++)
                T[(c + (u & 1)) * 136 + r + (u >> 1) * 8] = __float2half_rn(a[u]);
        }
    }
    __syncthreads();
    #pragma unroll
    for (int g = 0; g < 8; g++) {
        int lin = tid + g * 256;
        int d   = lin >> 4;
        int seg = lin & 15;
        uint4 v = *(const uint4*)((const uint8_t*)T + d * 272 + seg * 16);
        size_t dst = (((size_t)(b64 + jc0 + (seg >> 2)) * 128 + d) * 32) + (seg & 3) * 8;
        *(uint4*)(g_F + dst) = v;
    }

    __syncthreads();
    if (tid < 128) {
        g_q[row0 + tid] = qred[tid] + b_q[0];
        g_k[row0 + tid] = kred[tid] + b_k[0];
    }
}

// ---------------------------------------------------------------------------
// Kernel 1b: per-(b,i) exponentials + packed float4
// ---------------------------------------------------------------------------
__global__ __launch_bounds__(256) void k_ek()
{
    const int idx = blockIdx.x * 256 + threadIdx.x;
    float kk = g_k[idx];
    float e1 = __expf(kk);
    float e2 = __expf(0.01f * kk);
    g_ek[idx]  = e1;
    g_ek2[idx] = e2;
    g_kpk[idx] = make_float4(kk, e1, e2, 0.f);
}

// ---------------------------------------------------------------------------
// Kernel 2a: partial column sums. Bits along i live in a register word;
// per-i data is one LDS.128 broadcast. ~6 warp-inst per i.
// ---------------------------------------------------------------------------
__global__ __launch_bounds__(128) void k_denom()
{
    __shared__ float4 skp[256];

    const int tid = threadIdx.x;
    const int j   = blockIdx.x * 128 + tid;
    const int b   = blockIdx.y;
    const int i0  = blockIdx.z * 256;

    for (int s = tid; s < 256; s += 128)
        skp[s] = g_kpk[b * NN + i0 + s];
    __syncthreads();

    const float q   = g_q[b * NN + j];
    const float thr = -q;

    float t1 = 0.f, t2 = 0.f;
    int nb = 0;
    #pragma unroll
    for (int iw = 0; iw < 8; iw++) {
        uint32_t w = g_bitsT[(size_t)((i0 >> 5) + iw) * NN + j];
        nb += __popc(w);
        #pragma unroll
        for (int t = 0; t < 32; t++) {
            float4 kp = skp[iw * 32 + t];
            bool bit = (w >> t) & 1u;
            bool pos = kp.x > thr;
            if (bit && pos)  t1 += kp.y;
            if (bit && !pos) t2 += kp.z;
        }
    }
    g_part[blockIdx.z][b * NN + j] =
        __expf(q) * t1 + __expf(0.01f * q) * t2 + (float)(256 - nb);
}

// Kernel 2b: reduce partials -> rden + per-column pack (q, e^q*r, e^.01q*r, r)
__global__ __launch_bounds__(256) void k_rcp()
{
    const int idx = blockIdx.x * 256 + threadIdx.x;
    float s = 0.f;
    #pragma unroll
    for (int p = 0; p < 8; p++) s += g_part[p][idx];
    float r = __frcp_rn(s);
    float q = g_q[idx];
    g_jpk[idx] = make_float4(q, __expf(q) * r, __expf(0.01f * q) * r, r);
}

// ---------------------------------------------------------------------------
// Kernel 3: pipelined attention GEMM (unchanged from R8).
// ---------------------------------------------------------------------------
__global__ __launch_bounds__(256, 2) void k_attn(float* __restrict__ out)
{
    __shared__ __align__(16) uint8_t smd[2 * STAGE];

    const int tid  = threadIdx.x;
    const int lane = tid & 31;
    const int wid  = tid >> 5;
    const int wr   = wid >> 2;
    const int wc   = wid & 3;
    const int b    = blockIdx.y;
    const int i0   = blockIdx.x * 64;

    const uint32_t sb = smem_u32(smd);

    const float4* __restrict__ jp = g_jpk + b * NN;
    const __half* __restrict__ Fb = g_F + (size_t)b * DD * NN;

    float acc[8][4];
    #pragma unroll
    for (int i = 0; i < 8; i++)
        #pragma unroll
        for (int j = 0; j < 4; j++) acc[i][j] = 0.f;

    const int jj = (tid & 15) * 2;
    const int ib = tid >> 4;

    float kv[4], ekv[4], ek2v[4];
    #pragma unroll
    for (int g = 0; g < 4; g++) {
        int i = i0 + ib + g * 16;
        kv[g]   = g_k[b * NN + i];
        ekv[g]  = g_ek[b * NN + i];
        ek2v[g] = g_ek2[b * NN + i];
    }

    // ---- prologue: stage chunk 0 ----
    {
        #pragma unroll
        for (int g = 0; g < 2; g++) {
            int idx = tid + g * 256;
            int d = idx >> 2, seg = idx & 3;
            cpa16(sb + ASZ + (uint32_t)(d * PITCHB + seg * 16),
                  (const uint8_t*)Fb + idx * 16);
        }
        CP_COMMIT();
        float4 j0p = jp[jj], j1p = jp[jj + 1];
        #pragma unroll
        for (int g = 0; g < 4; g++) {
            int i = ib + g * 16;
            uint32_t w = g_bits[(size_t)(i0 + i) * 64];
            float z0 = kv[g] + j0p.x;
            float m0 = (z0 > 0.f) ? ekv[g] * j0p.y : ek2v[g] * j0p.z;
            float p0 = ((w >> jj) & 1u) ? m0 : j0p.w;
            float z1 = kv[g] + j1p.x;
            float m1 = (z1 > 0.f) ? ekv[g] * j1p.y : ek2v[g] * j1p.z;
            float p1 = ((w >> (jj + 1)) & 1u) ? m1 : j1p.w;
            *(uint32_t*)(smd + i * PITCHB + jj * 2) = pack2h(p0, p1);
        }
        CP_WAIT0();
        __syncthreads();
    }

    for (int c = 0; c < 64; c++) {
        const uint32_t cur = sb + (uint32_t)((c & 1) * STAGE);
        const uint32_t nxo = (uint32_t)(((c + 1) & 1) * STAGE);
        const bool pf = (c < 63);
        const int j0n = (c + 1) * 32;

        float4 j0p, j1p;
        uint32_t bw[4];
        if (pf) {
            const uint8_t* fsrc = (const uint8_t*)(Fb + (size_t)(j0n >> 5) * 4096);
            #pragma unroll
            for (int g = 0; g < 2; g++) {
                int idx = tid + g * 256;
                int d = idx >> 2, seg = idx & 3;
                cpa16(sb + nxo + ASZ + (uint32_t)(d * PITCHB + seg * 16), fsrc + idx * 16);
            }
            CP_COMMIT();
            j0p = jp[j0n + jj];
            j1p = jp[j0n + jj + 1];
            #pragma unroll
            for (int g = 0; g < 4; g++)
                bw[g] = g_bits[(size_t)(i0 + ib + g * 16) * 64 + (j0n >> 5)];
        }

        mma_chunk1<2>(acc, cur, cur + ASZ, wr, wc, lane);

        if (pf) {
            #pragma unroll
            for (int g = 0; g < 4; g++) {
                int i = ib + g * 16;
                float z0 = kv[g] + j0p.x;
                float m0 = (z0 > 0.f) ? ekv[g] * j0p.y : ek2v[g] * j0p.z;
                float p0 = ((bw[g] >> jj) & 1u) ? m0 : j0p.w;
                float z1 = kv[g] + j1p.x;
                float m1 = (z1 > 0.f) ? ekv[g] * j1p.y : ek2v[g] * j1p.z;
                float p1 = ((bw[g] >> (jj + 1)) & 1u) ? m1 : j1p.w;
                *(uint32_t*)(smd + nxo + i * PITCHB + jj * 2) = pack2h(p0, p1);
            }
            CP_WAIT0();
        }
        __syncthreads();
    }

    // epilogue
    #pragma unroll
    for (int it = 0; it < 2; it++) {
        int r = i0 + wr * 32 + it * 16 + (lane >> 2);
        #pragma unroll
        for (int nt = 0; nt < 4; nt++) {
            int c = wc * 32 + nt * 8 + (lane & 3) * 2;
            float* a = acc[it * 4 + nt];
            *(float2*)(out + ((size_t)b * NN + r) * DD + c)     = make_float2(a[0], a[1]);
            *(float2*)(out + ((size_t)b * NN + r + 8) * DD + c) = make_float2(a[2], a[3]);
        }
    }
}

// ---------------------------------------------------------------------------
extern "C" void kernel_launch(void* const* d_in, const int* in_sizes, int n_in,
                              void* d_out, int out_size)
{
    (void)in_sizes; (void)n_in; (void)out_size;
    const float* x     = (const float*)d_in[0];
    const float* adj   = (const float*)d_in[1];
    const float* W_emb = (const float*)d_in[2];
    const float* b_emb = (const float*)d_in[3];
    const float* w_q   = (const float*)d_in[4];
    const float* b_q   = (const float*)d_in[5];
    const float* w_k   = (const float*)d_in[6];
    const float* b_k   = (const float*)d_in[7];
    float* out = (float*)d_out;

    k_prep<<<512, 256>>>(adj);
    k_prepT<<<512, 256>>>();
    k_emb<<<(BB * NN) / 128, 256>>>(x, W_emb, b_emb, w_q, b_q, w_k, b_k);
    k_ek<<<(BB * NN) / 256, 256>>>();
    k_denom<<<dim3(NN / 128, BB, 8), 128>>>();
    k_rcp<<<(BB * NN) / 256, 256>>>();
    k_attn<<<dim3(NN / 64, BB), 256>>>(out);
}

// round 10
// speedup vs baseline: 1.0948x; 1.0460x over previous
#include <cuda_runtime.h>
#include <cuda_fp16.h>
#include <cstdint>

#define BB 16
#define NN 2048
#define DD 128

// scratch
__device__ float g_q[BB * NN];
__device__ float g_k[BB * NN];
__device__ float4 g_kpk[BB * NN];           // (k, e^k, e^.01k, 0)
__device__ float g_part[8][BB * NN];
__device__ float4 g_jpk[BB * NN];           // (q, e^q*rden, e^.01q*rden, rden)
__device__ uint32_t g_bits[NN * (NN / 32)];   // bits along j: word = i*64 + j/32
__device__ uint32_t g_bitsT[(NN / 32) * NN];  // bits along i: word = (i/32)*NN + j
// seq_fts^T single fp16, chunk-contiguous: [b][j/32][d][j%32]
__device__ __half g_F[(size_t)BB * DD * NN];

// ---------------------------------------------------------------------------
// helpers
// ---------------------------------------------------------------------------
__device__ __forceinline__ uint32_t smem_u32(const void* p) {
    uint32_t a;
    asm("{ .reg .u64 t; cvta.to.shared.u64 t, %1; cvt.u32.u64 %0, t; }" : "=r"(a) : "l"(p));
    return a;
}
__device__ __forceinline__ void cpa16(uint32_t dst, const void* src) {
    asm volatile("cp.async.cg.shared.global [%0], [%1], 16;" :: "r"(dst), "l"(src));
}
#define CP_COMMIT() asm volatile("cp.async.commit_group;")
#define CP_WAIT0()  asm volatile("cp.async.wait_group 0;" ::: "memory")

// pitch: 40 f16 = 80 bytes per 32-elem row (conflict-free for ldmatrix)
#define PITCHB 80
#define TILEB  (128 * PITCHB)    // 10240 bytes (128-row operand)
#define STAGE2 (2 * TILEB)       // A(128x32) + B(128dx32j) per stage

__device__ __forceinline__ void ldmA4(uint32_t base, int lane, uint32_t* a) {
    uint32_t addr = base + (uint32_t)((lane & 15) * PITCHB) + (uint32_t)(((lane >> 4) & 1) << 4);
    asm volatile("ldmatrix.sync.aligned.m8n8.x4.shared.b16 {%0,%1,%2,%3}, [%4];"
                 : "=r"(a[0]), "=r"(a[1]), "=r"(a[2]), "=r"(a[3]) : "r"(addr));
}
__device__ __forceinline__ void ldmB4(uint32_t base, int lane, uint32_t* r) {
    uint32_t addr = base + (uint32_t)(((lane & 7) + ((lane >> 4) << 3)) * PITCHB)
                         + (uint32_t)(((lane >> 3) & 1) << 4);
    asm volatile("ldmatrix.sync.aligned.m8n8.x4.shared.b16 {%0,%1,%2,%3}, [%4];"
                 : "=r"(r[0]), "=r"(r[1]), "=r"(r[2]), "=r"(r[3]) : "r"(addr));
}
__device__ __forceinline__ void mma16816h(float* d, const uint32_t* a, uint32_t b0, uint32_t b1) {
    asm volatile(
        "mma.sync.aligned.m16n8k16.row.col.f32.f16.f16.f32 "
        "{%0,%1,%2,%3}, {%4,%5,%6,%7}, {%8,%9}, {%0,%1,%2,%3};"
        : "+f"(d[0]), "+f"(d[1]), "+f"(d[2]), "+f"(d[3])
        : "r"(a[0]), "r"(a[1]), "r"(a[2]), "r"(a[3]), "r"(b0), "r"(b1));
}

__device__ __forceinline__ void split2h(float v0, float v1, uint32_t& hw, uint32_t& lw) {
    __half h0 = __float2half_rn(v0);
    __half h1 = __float2half_rn(v1);
    __half2 hh; hh.x = h0; hh.y = h1;
    __half2 ll;
    ll.x = __float2half_rn(v0 - __half2float(h0));
    ll.y = __float2half_rn(v1 - __half2float(h1));
    hw = *(uint32_t*)&hh;
    lw = *(uint32_t*)&ll;
}
__device__ __forceinline__ uint32_t pack2h(float v0, float v1) {
    __half2 hh; hh.x = __float2half_rn(v0); hh.y = __float2half_rn(v1);
    return *(uint32_t*)&hh;
}

// 3-term split mainloop (k_emb)
template <int NIT>
__device__ __forceinline__ void mma_chunk3(float (*acc)[4],
                                           uint32_t sAH, uint32_t sAL,
                                           uint32_t sBH, uint32_t sBL,
                                           int wr, int wc, int lane) {
    #pragma unroll
    for (int ks = 0; ks < 2; ks++) {
        uint32_t bh[8], bl[8];
        #pragma unroll
        for (int ntp = 0; ntp < 2; ntp++) {
            uint32_t boff = (uint32_t)((wc * 32 + ntp * 16) * PITCHB + ks * 32);
            ldmB4(sBH + boff, lane, bh + ntp * 4);
            ldmB4(sBL + boff, lane, bl + ntp * 4);
        }
        #pragma unroll
        for (int it = 0; it < NIT; it++) {
            uint32_t aoff = (uint32_t)(((wr * NIT + it) * 16) * PITCHB + ks * 32);
            uint32_t ah[4], al[4];
            ldmA4(sAH + aoff, lane, ah);
            ldmA4(sAL + aoff, lane, al);
            #pragma unroll
            for (int nt = 0; nt < 4; nt++) {
                mma16816h(acc[it * 4 + nt], ah, bh[nt * 2], bh[nt * 2 + 1]);
                mma16816h(acc[it * 4 + nt], ah, bl[nt * 2], bl[nt * 2 + 1]);
                mma16816h(acc[it * 4 + nt], al, bh[nt * 2], bh[nt * 2 + 1]);
            }
        }
    }
}

// single-term mainloop (k_attn)
template <int NIT>
__device__ __forceinline__ void mma_chunk1(float (*acc)[4],
                                           uint32_t sA, uint32_t sB,
                                           int wr, int wc, int lane) {
    #pragma unroll
    for (int ks = 0; ks < 2; ks++) {
        uint32_t bf[8];
        #pragma unroll
        for (int ntp = 0; ntp < 2; ntp++) {
            uint32_t boff = (uint32_t)((wc * 32 + ntp * 16) * PITCHB + ks * 32);
            ldmB4(sB + boff, lane, bf + ntp * 4);
        }
        #pragma unroll
        for (int it = 0; it < NIT; it++) {
            uint32_t aoff = (uint32_t)(((wr * NIT + it) * 16) * PITCHB + ks * 32);
            uint32_t ah[4];
            ldmA4(sA + aoff, lane, ah);
            #pragma unroll
            for (int nt = 0; nt < 4; nt++)
                mma16816h(acc[it * 4 + nt], ah, bf[nt * 2], bf[nt * 2 + 1]);
        }
    }
}

// ---------------------------------------------------------------------------
// Kernel 0: fused bit-pack + bit-transpose. Warp handles one 32x32 adj block.
// ---------------------------------------------------------------------------
__global__ __launch_bounds__(256) void k_prep2(const float* __restrict__ adj)
{
    const int lane = threadIdx.x & 31;
    const int wg   = blockIdx.x * 8 + (threadIdx.x >> 5);   // 0..4095
    const int ic   = wg >> 6;    // i-chunk 0..63
    const int jw   = wg & 63;    // j-word  0..63

    // phase 1: bits along j. lane t ends up owning row ic*32+t's word.
    uint32_t keep = 0;
    #pragma unroll
    for (int t = 0; t < 32; t++) {
        float v = adj[(size_t)(ic * 32 + t) * NN + jw * 32 + lane];
        uint32_t m = __ballot_sync(0xffffffffu, v != 0.f);
        if (lane == t) keep = m;
    }
    g_bits[(size_t)(ic * 32 + lane) * 64 + jw] = keep;

    // phase 2: in-register transpose -> bits along i, lane t owns column jw*32+t.
    uint32_t keepT = 0;
    #pragma unroll
    for (int t = 0; t < 32; t++) {
        uint32_t m = __ballot_sync(0xffffffffu, (keep >> t) & 1u);
        if (lane == t) keepT = m;
    }
    g_bitsT[(size_t)ic * NN + jw * 32 + lane] = keepT;
}

// ---------------------------------------------------------------------------
// Kernel 1: seq_fts GEMM + q/k + kpk exponentials (k_ek fused in).
// ---------------------------------------------------------------------------
__global__ __launch_bounds__(256) void k_emb(
    const float* __restrict__ x, const float* __restrict__ W,
    const float* __restrict__ b_emb,
    const float* __restrict__ w_q, const float* __restrict__ b_q,
    const float* __restrict__ w_k, const float* __restrict__ b_k)
{
    __shared__ __align__(16) uint8_t sm[4 * TILEB];
    __shared__ float qred[128], kred[128];

    const int tid  = threadIdx.x;
    const int lane = tid & 31;
    const int wid  = tid >> 5;
    const int wr   = wid >> 2;
    const int wc   = wid & 3;
    const int blk  = blockIdx.x;
    const size_t row0 = (size_t)blk * 128;

    if (tid < 128) { qred[tid] = 0.f; kred[tid] = 0.f; }

    const uint32_t sb  = smem_u32(sm);
    const uint32_t sAH = sb, sAL = sb + TILEB, sBH = sb + 2 * TILEB, sBL = sb + 3 * TILEB;

    float acc[16][4];
    #pragma unroll
    for (int i = 0; i < 16; i++)
        #pragma unroll
        for (int j = 0; j < 4; j++) acc[i][j] = 0.f;

    const int jj = (tid & 15) * 2;
    const int rb = tid >> 4;

    for (int k0 = 0; k0 < DD; k0 += 32) {
        __syncthreads();
        #pragma unroll
        for (int g = 0; g < 8; g++) {
            int r = rb + g * 16;
            float2 xv = *(const float2*)(x + (row0 + r) * DD + k0 + jj);
            float2 wv = *(const float2*)(W + (size_t)r * DD + k0 + jj);
            uint32_t hw, lw;
            split2h(xv.x, xv.y, hw, lw);
            *(uint32_t*)(sm + (size_t)0 * TILEB + r * PITCHB + jj * 2) = hw;
            *(uint32_t*)(sm + (size_t)1 * TILEB + r * PITCHB + jj * 2) = lw;
            split2h(wv.x, wv.y, hw, lw);
            *(uint32_t*)(sm + (size_t)2 * TILEB + r * PITCHB + jj * 2) = hw;
            *(uint32_t*)(sm + (size_t)3 * TILEB + r * PITCHB + jj * 2) = lw;
        }
        __syncthreads();
        mma_chunk3<4>(acc, sAH, sAL, sBH, sBL, wr, wc, lane);
    }

    float2 be[4], wq2[4], wk2[4];
    #pragma unroll
    for (int nt = 0; nt < 4; nt++) {
        int c = wc * 32 + nt * 8 + (lane & 3) * 2;
        be[nt]  = *(const float2*)(b_emb + c);
        wq2[nt] = *(const float2*)(w_q + c);
        wk2[nt] = *(const float2*)(w_k + c);
    }
    __syncthreads();

    #pragma unroll
    for (int it = 0; it < 4; it++) {
        float q0 = 0.f, q8 = 0.f, kk0 = 0.f, kk8 = 0.f;
        #pragma unroll
        for (int nt = 0; nt < 4; nt++) {
            float* a = acc[it * 4 + nt];
            a[0] += be[nt].x; a[1] += be[nt].y;
            a[2] += be[nt].x; a[3] += be[nt].y;
            q0 += a[0] * wq2[nt].x + a[1] * wq2[nt].y;
            q8 += a[2] * wq2[nt].x + a[3] * wq2[nt].y;
            kk0 += a[0] * wk2[nt].x + a[1] * wk2[nt].y;
            kk8 += a[2] * wk2[nt].x + a[3] * wk2[nt].y;
        }
        #pragma unroll
        for (int off = 1; off <= 2; off <<= 1) {
            q0 += __shfl_xor_sync(0xffffffffu, q0, off);
            q8 += __shfl_xor_sync(0xffffffffu, q8, off);
            kk0 += __shfl_xor_sync(0xffffffffu, kk0, off);
            kk8 += __shfl_xor_sync(0xffffffffu, kk8, off);
        }
        if ((lane & 3) == 0) {
            int r = wr * 64 + it * 16 + (lane >> 2);
            atomicAdd(&qred[r], q0);
            atomicAdd(&qred[r + 8], q8);
            atomicAdd(&kred[r], kk0);
            atomicAdd(&kred[r + 8], kk8);
        }
    }

    // transpose + store single fp16
    __half* T = (__half*)sm;
    const int b64 = (blk >> 4) * 64;
    const int jc0 = (blk & 15) * 4;

    __syncthreads();
    #pragma unroll
    for (int it = 0; it < 4; it++) {
        int r = wr * 64 + it * 16 + (lane >> 2);
        #pragma unroll
        for (int nt = 0; nt < 4; nt++) {
            int c = wc * 32 + nt * 8 + (lane & 3) * 2;
            float* a = acc[it * 4 + nt];
            #pragma unroll
            for (int u = 0; u < 4; u++)
                T[(c + (u & 1)) * 136 + r + (u >> 1) * 8] = __float2half_rn(a[u]);
        }
    }
    __syncthreads();
    #pragma unroll
    for (int g = 0; g < 8; g++) {
        int lin = tid + g * 256;
        int d   = lin >> 4;
        int seg = lin & 15;
        uint4 v = *(const uint4*)((const uint8_t*)T + d * 272 + seg * 16);
        size_t dst = (((size_t)(b64 + jc0 + (seg >> 2)) * 128 + d) * 32) + (seg & 3) * 8;
        *(uint4*)(g_F + dst) = v;
    }

    __syncthreads();
    if (tid < 128) {
        float qv = qred[tid] + b_q[0];
        float kk = kred[tid] + b_k[0];
        g_q[row0 + tid] = qv;
        g_k[row0 + tid] = kk;
        g_kpk[row0 + tid] = make_float4(kk, __expf(kk), __expf(0.01f * kk), 0.f);
    }
}

// ---------------------------------------------------------------------------
// Kernel 2a: partial column sums (register bit word + LDS.128 per i)
// ---------------------------------------------------------------------------
__global__ __launch_bounds__(128) void k_denom()
{
    __shared__ float4 skp[256];

    const int tid = threadIdx.x;
    const int j   = blockIdx.x * 128 + tid;
    const int b   = blockIdx.y;
    const int i0  = blockIdx.z * 256;

    for (int s = tid; s < 256; s += 128)
        skp[s] = g_kpk[b * NN + i0 + s];
    __syncthreads();

    const float q   = g_q[b * NN + j];
    const float thr = -q;

    float t1 = 0.f, t2 = 0.f;
    int nb = 0;
    #pragma unroll
    for (int iw = 0; iw < 8; iw++) {
        uint32_t w = g_bitsT[(size_t)((i0 >> 5) + iw) * NN + j];
        nb += __popc(w);
        #pragma unroll
        for (int t = 0; t < 32; t++) {
            float4 kp = skp[iw * 32 + t];
            bool bit = (w >> t) & 1u;
            bool pos = kp.x > thr;
            if (bit && pos)  t1 += kp.y;
            if (bit && !pos) t2 += kp.z;
        }
    }
    g_part[blockIdx.z][b * NN + j] =
        __expf(q) * t1 + __expf(0.01f * q) * t2 + (float)(256 - nb);
}

// Kernel 2b: reduce partials -> rden + per-column pack
__global__ __launch_bounds__(256) void k_rcp()
{
    const int idx = blockIdx.x * 256 + threadIdx.x;
    float s = 0.f;
    #pragma unroll
    for (int p = 0; p < 8; p++) s += g_part[p][idx];
    float r = __frcp_rn(s);
    float q = g_q[idx];
    g_jpk[idx] = make_float4(q, __expf(q) * r, __expf(0.01f * q) * r, r);
}

// ---------------------------------------------------------------------------
// Kernel 3: pipelined attention GEMM. Tile 128i x 128d, j-chunk 32,
// double-buffered, per-i constants in smem. grid (16, 16).
// ---------------------------------------------------------------------------
__global__ __launch_bounds__(256, 2) void k_attn(float* __restrict__ out)
{
    __shared__ __align__(16) uint8_t smd[2 * STAGE2];
    __shared__ float4 skp[128];

    const int tid  = threadIdx.x;
    const int lane = tid & 31;
    const int wid  = tid >> 5;
    const int wr   = wid >> 2;        // 0..1 : 64-row group
    const int wc   = wid & 3;         // 0..3 : 32-col group
    const int b    = blockIdx.y;
    const int i0   = blockIdx.x * 128;

    const uint32_t sb = smem_u32(smd);

    const float4* __restrict__ jp = g_jpk + b * NN;
    const __half* __restrict__ Fb = g_F + (size_t)b * DD * NN;

    float acc[16][4];
    #pragma unroll
    for (int i = 0; i < 16; i++)
        #pragma unroll
        for (int j = 0; j < 4; j++) acc[i][j] = 0.f;

    const int jj = (tid & 15) * 2;
    const int ib = tid >> 4;

    // ---- prologue ----
    if (tid < 128) skp[tid] = g_kpk[b * NN + i0 + tid];
    #pragma unroll
    for (int g = 0; g < 2; g++) {
        int idx = tid + g * 256;
        int d = idx >> 2, seg = idx & 3;
        cpa16(sb + TILEB + (uint32_t)(d * PITCHB + seg * 16),
              (const uint8_t*)Fb + idx * 16);
    }
    CP_COMMIT();
    __syncthreads();   // skp visible

    {
        float4 j0p = jp[jj], j1p = jp[jj + 1];
        #pragma unroll
        for (int g = 0; g < 8; g++) {
            int i = ib + g * 16;
            float4 kp = skp[i];
            uint32_t w = g_bits[(size_t)(i0 + i) * 64];
            float z0 = kp.x + j0p.x;
            float m0 = (z0 > 0.f) ? kp.y * j0p.y : kp.z * j0p.z;
            float p0 = ((w >> jj) & 1u) ? m0 : j0p.w;
            float z1 = kp.x + j1p.x;
            float m1 = (z1 > 0.f) ? kp.y * j1p.y : kp.z * j1p.z;
            float p1 = ((w >> (jj + 1)) & 1u) ? m1 : j1p.w;
            *(uint32_t*)(smd + i * PITCHB + jj * 2) = pack2h(p0, p1);
        }
        CP_WAIT0();
        __syncthreads();
    }

    for (int c = 0; c < 64; c++) {
        const uint32_t cur = sb + (uint32_t)((c & 1) * STAGE2);
        const uint32_t nxo = (uint32_t)(((c + 1) & 1) * STAGE2);
        const bool pf = (c < 63);
        const int j0n = (c + 1) * 32;

        float4 j0p, j1p;
        uint32_t bw[8];
        if (pf) {
            const uint8_t* fsrc = (const uint8_t*)(Fb + (size_t)(j0n >> 5) * 4096);
            #pragma unroll
            for (int g = 0; g < 2; g++) {
                int idx = tid + g * 256;
                int d = idx >> 2, seg = idx & 3;
                cpa16(sb + nxo + TILEB + (uint32_t)(d * PITCHB + seg * 16), fsrc + idx * 16);
            }
            CP_COMMIT();
            j0p = jp[j0n + jj];
            j1p = jp[j0n + jj + 1];
            #pragma unroll
            for (int g = 0; g < 8; g++)
                bw[g] = g_bits[(size_t)(i0 + ib + g * 16) * 64 + (j0n >> 5)];
        }

        // MMA on current stage (128 rows)
        mma_chunk1<4>(acc, cur, cur + TILEB, wr, wc, lane);

        // compute + store next A
        if (pf) {
            #pragma unroll
            for (int g = 0; g < 8; g++) {
                int i = ib + g * 16;
                float4 kp = skp[i];
                float z0 = kp.x + j0p.x;
                float m0 = (z0 > 0.f) ? kp.y * j0p.y : kp.z * j0p.z;
                float p0 = ((bw[g] >> jj) & 1u) ? m0 : j0p.w;
                float z1 = kp.x + j1p.x;
                float m1 = (z1 > 0.f) ? kp.y * j1p.y : kp.z * j1p.z;
                float p1 = ((bw[g] >> (jj + 1)) & 1u) ? m1 : j1p.w;
                *(uint32_t*)(smd + nxo + i * PITCHB + jj * 2) = pack2h(p0, p1);
            }
            CP_WAIT0();
        }
        __syncthreads();
    }

    // epilogue
    #pragma unroll
    for (int it = 0; it < 4; it++) {
        int r = i0 + wr * 64 + it * 16 + (lane >> 2);
        #pragma unroll
        for (int nt = 0; nt < 4; nt++) {
            int c = wc * 32 + nt * 8 + (lane & 3) * 2;
            float* a = acc[it * 4 + nt];
            *(float2*)(out + ((size_t)b * NN + r) * DD + c)     = make_float2(a[0], a[1]);
            *(float2*)(out + ((size_t)b * NN + r + 8) * DD + c) = make_float2(a[2], a[3]);
        }
    }
}

// ---------------------------------------------------------------------------
extern "C" void kernel_launch(void* const* d_in, const int* in_sizes, int n_in,
                              void* d_out, int out_size)
{
    (void)in_sizes; (void)n_in; (void)out_size;
    const float* x     = (const float*)d_in[0];
    const float* adj   = (const float*)d_in[1];
    const float* W_emb = (const float*)d_in[2];
    const float* b_emb = (const float*)d_in[3];
    const float* w_q   = (const float*)d_in[4];
    const float* b_q   = (const float*)d_in[5];
    const float* w_k   = (const float*)d_in[6];
    const float* b_k   = (const float*)d_in[7];
    float* out = (float*)d_out;

    k_prep2<<<512, 256>>>(adj);
    k_emb<<<(BB * NN) / 128, 256>>>(x, W_emb, b_emb, w_q, b_q, w_k, b_k);
    k_denom<<<dim3(NN / 128, BB, 8), 128>>>();
    k_rcp<<<(BB * NN) / 256, 256>>>();
    k_attn<<<dim3(NN / 128, BB), 256>>>(out);
}

// round 11
// speedup vs baseline: 1.1630x; 1.0623x over previous
#include <cuda_runtime.h>
#include <cuda_fp16.h>
#include <cstdint>

#define BB 16
#define NN 2048
#define DD 128

// scratch
__device__ float g_q[BB * NN];
__device__ float g_k[BB * NN];
__device__ float4 g_kpk[BB * NN];           // (k, e^k, e^.01k, 0)
__device__ float g_part[8][BB * NN];
__device__ float4 g_jpk[BB * NN];           // (q, e^q*rden, e^.01q*rden, rden)
__device__ int   g_cnt[BB * (NN / 128)];    // last-block counters (self-resetting)
__device__ uint32_t g_bits[NN * (NN / 32)];   // bits along j: word = i*64 + j/32
__device__ uint32_t g_bitsT[(NN / 32) * NN];  // bits along i: word = (i/32)*NN + j
// seq_fts^T single fp16, chunk-contiguous: [b][j/32][d][j%32]
__device__ __half g_F[(size_t)BB * DD * NN];

// ---------------------------------------------------------------------------
// helpers
// ---------------------------------------------------------------------------
__device__ __forceinline__ uint32_t smem_u32(const void* p) {
    uint32_t a;
    asm("{ .reg .u64 t; cvta.to.shared.u64 t, %1; cvt.u32.u64 %0, t; }" : "=r"(a) : "l"(p));
    return a;
}
__device__ __forceinline__ void cpa16(uint32_t dst, const void* src) {
    asm volatile("cp.async.cg.shared.global [%0], [%1], 16;" :: "r"(dst), "l"(src));
}
#define CP_COMMIT() asm volatile("cp.async.commit_group;")
#define CP_WAIT0()  asm volatile("cp.async.wait_group 0;" ::: "memory")
#define CP_WAIT1()  asm volatile("cp.async.wait_group 1;" ::: "memory")

// pitch: 40 f16 = 80 bytes per 32-elem row (conflict-free for ldmatrix)
#define PITCHB 80
#define TILEB  (128 * PITCHB)    // 10240 bytes (128-row operand)
// k_attn dynamic smem layout: A0 A1 | B0 B1 B2 | skp
#define OFF_B   (2 * TILEB)
#define OFF_SKP (5 * TILEB)
#define SMEM_ATTN (5 * TILEB + 2048)

__device__ __forceinline__ void ldmA4(uint32_t base, int lane, uint32_t* a) {
    uint32_t addr = base + (uint32_t)((lane & 15) * PITCHB) + (uint32_t)(((lane >> 4) & 1) << 4);
    asm volatile("ldmatrix.sync.aligned.m8n8.x4.shared.b16 {%0,%1,%2,%3}, [%4];"
                 : "=r"(a[0]), "=r"(a[1]), "=r"(a[2]), "=r"(a[3]) : "r"(addr));
}
__device__ __forceinline__ void ldmB4(uint32_t base, int lane, uint32_t* r) {
    uint32_t addr = base + (uint32_t)(((lane & 7) + ((lane >> 4) << 3)) * PITCHB)
                         + (uint32_t)(((lane >> 3) & 1) << 4);
    asm volatile("ldmatrix.sync.aligned.m8n8.x4.shared.b16 {%0,%1,%2,%3}, [%4];"
                 : "=r"(r[0]), "=r"(r[1]), "=r"(r[2]), "=r"(r[3]) : "r"(addr));
}
__device__ __forceinline__ void mma16816h(float* d, const uint32_t* a, uint32_t b0, uint32_t b1) {
    asm volatile(
        "mma.sync.aligned.m16n8k16.row.col.f32.f16.f16.f32 "
        "{%0,%1,%2,%3}, {%4,%5,%6,%7}, {%8,%9}, {%0,%1,%2,%3};"
        : "+f"(d[0]), "+f"(d[1]), "+f"(d[2]), "+f"(d[3])
        : "r"(a[0]), "r"(a[1]), "r"(a[2]), "r"(a[3]), "r"(b0), "r"(b1));
}

__device__ __forceinline__ void split2h(float v0, float v1, uint32_t& hw, uint32_t& lw) {
    __half h0 = __float2half_rn(v0);
    __half h1 = __float2half_rn(v1);
    __half2 hh; hh.x = h0; hh.y = h1;
    __half2 ll;
    ll.x = __float2half_rn(v0 - __half2float(h0));
    ll.y = __float2half_rn(v1 - __half2float(h1));
    hw = *(uint32_t*)&hh;
    lw = *(uint32_t*)&ll;
}
__device__ __forceinline__ uint32_t pack2h(float v0, float v1) {
    __half2 hh; hh.x = __float2half_rn(v0); hh.y = __float2half_rn(v1);
    return *(uint32_t*)&hh;
}

// 3-term split mainloop (k_emb)
template <int NIT>
__device__ __forceinline__ void mma_chunk3(float (*acc)[4],
                                           uint32_t sAH, uint32_t sAL,
                                           uint32_t sBH, uint32_t sBL,
                                           int wr, int wc, int lane) {
    #pragma unroll
    for (int ks = 0; ks < 2; ks++) {
        uint32_t bh[8], bl[8];
        #pragma unroll
        for (int ntp = 0; ntp < 2; ntp++) {
            uint32_t boff = (uint32_t)((wc * 32 + ntp * 16) * PITCHB + ks * 32);
            ldmB4(sBH + boff, lane, bh + ntp * 4);
            ldmB4(sBL + boff, lane, bl + ntp * 4);
        }
        #pragma unroll
        for (int it = 0; it < NIT; it++) {
            uint32_t aoff = (uint32_t)(((wr * NIT + it) * 16) * PITCHB + ks * 32);
            uint32_t ah[4], al[4];
            ldmA4(sAH + aoff, lane, ah);
            ldmA4(sAL + aoff, lane, al);
            #pragma unroll
            for (int nt = 0; nt < 4; nt++) {
                mma16816h(acc[it * 4 + nt], ah, bh[nt * 2], bh[nt * 2 + 1]);
                mma16816h(acc[it * 4 + nt], ah, bl[nt * 2], bl[nt * 2 + 1]);
                mma16816h(acc[it * 4 + nt], al, bh[nt * 2], bh[nt * 2 + 1]);
            }
        }
    }
}

// single-term mainloop (k_attn)
template <int NIT>
__device__ __forceinline__ void mma_chunk1(float (*acc)[4],
                                           uint32_t sA, uint32_t sB,
                                           int wr, int wc, int lane) {
    #pragma unroll
    for (int ks = 0; ks < 2; ks++) {
        uint32_t bf[8];
        #pragma unroll
        for (int ntp = 0; ntp < 2; ntp++) {
            uint32_t boff = (uint32_t)((wc * 32 + ntp * 16) * PITCHB + ks * 32);
            ldmB4(sB + boff, lane, bf + ntp * 4);
        }
        #pragma unroll
        for (int it = 0; it < NIT; it++) {
            uint32_t aoff = (uint32_t)(((wr * NIT + it) * 16) * PITCHB + ks * 32);
            uint32_t ah[4];
            ldmA4(sA + aoff, lane, ah);
            #pragma unroll
            for (int nt = 0; nt < 4; nt++)
                mma16816h(acc[it * 4 + nt], ah, bf[nt * 2], bf[nt * 2 + 1]);
        }
    }
}

// ---------------------------------------------------------------------------
// Kernel 0: fused bit-pack + bit-transpose.
// ---------------------------------------------------------------------------
__global__ __launch_bounds__(256) void k_prep2(const float* __restrict__ adj)
{
    const int lane = threadIdx.x & 31;
    const int wg   = blockIdx.x * 8 + (threadIdx.x >> 5);   // 0..4095
    const int ic   = wg >> 6;    // i-chunk 0..63
    const int jw   = wg & 63;    // j-word  0..63

    uint32_t keep = 0;
    #pragma unroll
    for (int t = 0; t < 32; t++) {
        float v = adj[(size_t)(ic * 32 + t) * NN + jw * 32 + lane];
        uint32_t m = __ballot_sync(0xffffffffu, v != 0.f);
        if (lane == t) keep = m;
    }
    g_bits[(size_t)(ic * 32 + lane) * 64 + jw] = keep;

    uint32_t keepT = 0;
    #pragma unroll
    for (int t = 0; t < 32; t++) {
        uint32_t m = __ballot_sync(0xffffffffu, (keep >> t) & 1u);
        if (lane == t) keepT = m;
    }
    g_bitsT[(size_t)ic * NN + jw * 32 + lane] = keepT;
}

// ---------------------------------------------------------------------------
// Kernel 1: seq_fts GEMM + q/k + kpk exponentials.
// ---------------------------------------------------------------------------
__global__ __launch_bounds__(256) void k_emb(
    const float* __restrict__ x, const float* __restrict__ W,
    const float* __restrict__ b_emb,
    const float* __restrict__ w_q, const float* __restrict__ b_q,
    const float* __restrict__ w_k, const float* __restrict__ b_k)
{
    __shared__ __align__(16) uint8_t sm[4 * TILEB];
    __shared__ float qred[128], kred[128];

    const int tid  = threadIdx.x;
    const int lane = tid & 31;
    const int wid  = tid >> 5;
    const int wr   = wid >> 2;
    const int wc   = wid & 3;
    const int blk  = blockIdx.x;
    const size_t row0 = (size_t)blk * 128;

    if (tid < 128) { qred[tid] = 0.f; kred[tid] = 0.f; }

    const uint32_t sb  = smem_u32(sm);
    const uint32_t sAH = sb, sAL = sb + TILEB, sBH = sb + 2 * TILEB, sBL = sb + 3 * TILEB;

    float acc[16][4];
    #pragma unroll
    for (int i = 0; i < 16; i++)
        #pragma unroll
        for (int j = 0; j < 4; j++) acc[i][j] = 0.f;

    const int jj = (tid & 15) * 2;
    const int rb = tid >> 4;

    for (int k0 = 0; k0 < DD; k0 += 32) {
        __syncthreads();
        #pragma unroll
        for (int g = 0; g < 8; g++) {
            int r = rb + g * 16;
            float2 xv = *(const float2*)(x + (row0 + r) * DD + k0 + jj);
            float2 wv = *(const float2*)(W + (size_t)r * DD + k0 + jj);
            uint32_t hw, lw;
            split2h(xv.x, xv.y, hw, lw);
            *(uint32_t*)(sm + (size_t)0 * TILEB + r * PITCHB + jj * 2) = hw;
            *(uint32_t*)(sm + (size_t)1 * TILEB + r * PITCHB + jj * 2) = lw;
            split2h(wv.x, wv.y, hw, lw);
            *(uint32_t*)(sm + (size_t)2 * TILEB + r * PITCHB + jj * 2) = hw;
            *(uint32_t*)(sm + (size_t)3 * TILEB + r * PITCHB + jj * 2) = lw;
        }
        __syncthreads();
        mma_chunk3<4>(acc, sAH, sAL, sBH, sBL, wr, wc, lane);
    }

    float2 be[4], wq2[4], wk2[4];
    #pragma unroll
    for (int nt = 0; nt < 4; nt++) {
        int c = wc * 32 + nt * 8 + (lane & 3) * 2;
        be[nt]  = *(const float2*)(b_emb + c);
        wq2[nt] = *(const float2*)(w_q + c);
        wk2[nt] = *(const float2*)(w_k + c);
    }
    __syncthreads();

    #pragma unroll
    for (int it = 0; it < 4; it++) {
        float q0 = 0.f, q8 = 0.f, kk0 = 0.f, kk8 = 0.f;
        #pragma unroll
        for (int nt = 0; nt < 4; nt++) {
            float* a = acc[it * 4 + nt];
            a[0] += be[nt].x; a[1] += be[nt].y;
            a[2] += be[nt].x; a[3] += be[nt].y;
            q0 += a[0] * wq2[nt].x + a[1] * wq2[nt].y;
            q8 += a[2] * wq2[nt].x + a[3] * wq2[nt].y;
            kk0 += a[0] * wk2[nt].x + a[1] * wk2[nt].y;
            kk8 += a[2] * wk2[nt].x + a[3] * wk2[nt].y;
        }
        #pragma unroll
        for (int off = 1; off <= 2; off <<= 1) {
            q0 += __shfl_xor_sync(0xffffffffu, q0, off);
            q8 += __shfl_xor_sync(0xffffffffu, q8, off);
            kk0 += __shfl_xor_sync(0xffffffffu, kk0, off);
            kk8 += __shfl_xor_sync(0xffffffffu, kk8, off);
        }
        if ((lane & 3) == 0) {
            int r = wr * 64 + it * 16 + (lane >> 2);
            atomicAdd(&qred[r], q0);
            atomicAdd(&qred[r + 8], q8);
            atomicAdd(&kred[r], kk0);
            atomicAdd(&kred[r + 8], kk8);
        }
    }

    // transpose + store single fp16
    __half* T = (__half*)sm;
    const int b64 = (blk >> 4) * 64;
    const int jc0 = (blk & 15) * 4;

    __syncthreads();
    #pragma unroll
    for (int it = 0; it < 4; it++) {
        int r = wr * 64 + it * 16 + (lane >> 2);
        #pragma unroll
        for (int nt = 0; nt < 4; nt++) {
            int c = wc * 32 + nt * 8 + (lane & 3) * 2;
            float* a = acc[it * 4 + nt];
            #pragma unroll
            for (int u = 0; u < 4; u++)
                T[(c + (u & 1)) * 136 + r + (u >> 1) * 8] = __float2half_rn(a[u]);
        }
    }
    __syncthreads();
    #pragma unroll
    for (int g = 0; g < 8; g++) {
        int lin = tid + g * 256;
        int d   = lin >> 4;
        int seg = lin & 15;
        uint4 v = *(const uint4*)((const uint8_t*)T + d * 272 + seg * 16);
        size_t dst = (((size_t)(b64 + jc0 + (seg >> 2)) * 128 + d) * 32) + (seg & 3) * 8;
        *(uint4*)(g_F + dst) = v;
    }

    __syncthreads();
    if (tid < 128) {
        float qv = qred[tid] + b_q[0];
        float kk = kred[tid] + b_k[0];
        g_q[row0 + tid] = qv;
        g_k[row0 + tid] = kk;
        g_kpk[row0 + tid] = make_float4(kk, __expf(kk), __expf(0.01f * kk), 0.f);
    }
}

// ---------------------------------------------------------------------------
// Kernel 2: partial column sums + fused last-block reduce -> g_jpk.
// ---------------------------------------------------------------------------
__global__ __launch_bounds__(128) void k_denom()
{
    __shared__ float4 skp[256];
    __shared__ int slast;

    const int tid = threadIdx.x;
    const int j   = blockIdx.x * 128 + tid;
    const int b   = blockIdx.y;
    const int i0  = blockIdx.z * 256;

    for (int s = tid; s < 256; s += 128)
        skp[s] = g_kpk[b * NN + i0 + s];
    __syncthreads();

    const float q   = g_q[b * NN + j];
    const float thr = -q;

    float t1 = 0.f, t2 = 0.f;
    int nb = 0;
    #pragma unroll
    for (int iw = 0; iw < 8; iw++) {
        uint32_t w = g_bitsT[(size_t)((i0 >> 5) + iw) * NN + j];
        nb += __popc(w);
        #pragma unroll
        for (int t = 0; t < 32; t++) {
            float4 kp = skp[iw * 32 + t];
            bool bit = (w >> t) & 1u;
            bool pos = kp.x > thr;
            if (bit && pos)  t1 += kp.y;
            if (bit && !pos) t2 += kp.z;
        }
    }
    g_part[blockIdx.z][b * NN + j] =
        __expf(q) * t1 + __expf(0.01f * q) * t2 + (float)(256 - nb);

    // last-block reduction (threadFenceReduction pattern)
    __threadfence();
    if (tid == 0) {
        int old = atomicAdd(&g_cnt[b * (NN / 128) + blockIdx.x], 1);
        slast = (old == 7) ? 1 : 0;
    }
    __syncthreads();
    if (slast) {
        float s = 0.f;
        #pragma unroll
        for (int p = 0; p < 8; p++) s += g_part[p][b * NN + j];
        float r = __frcp_rn(s);
        g_jpk[b * NN + j] = make_float4(q, __expf(q) * r, __expf(0.01f * q) * r, r);
        if (tid == 0) g_cnt[b * (NN / 128) + blockIdx.x] = 0;  // reset for graph replay
    }
}

// ---------------------------------------------------------------------------
// Kernel 3: pipelined attention GEMM. Tile 128i x 128d, j-chunk 32,
// A double-buffered, B triple-buffered via cp.async wait_group 1.
// ---------------------------------------------------------------------------
__global__ __launch_bounds__(256, 2) void k_attn(float* __restrict__ out)
{
    extern __shared__ __align__(16) uint8_t smd[];
    float4* skp = (float4*)(smd + OFF_SKP);

    const int tid  = threadIdx.x;
    const int lane = tid & 31;
    const int wid  = tid >> 5;
    const int wr   = wid >> 2;        // 0..1 : 64-row group
    const int wc   = wid & 3;         // 0..3 : 32-col group
    const int b    = blockIdx.y;
    const int i0   = blockIdx.x * 128;

    const uint32_t sb = smem_u32(smd);

    const float4* __restrict__ jp = g_jpk + b * NN;
    const __half* __restrict__ Fb = g_F + (size_t)b * DD * NN;

    float acc[16][4];
    #pragma unroll
    for (int i = 0; i < 16; i++)
        #pragma unroll
        for (int j = 0; j < 4; j++) acc[i][j] = 0.f;

    const int jj = (tid & 15) * 2;
    const int ib = tid >> 4;

    // ---- prologue: skp, B0, B1 in flight; A0 generated ----
    if (tid < 128) skp[tid] = g_kpk[b * NN + i0 + tid];
    #pragma unroll
    for (int s = 0; s < 2; s++) {
        const uint8_t* fsrc = (const uint8_t*)(Fb + (size_t)s * 4096);
        #pragma unroll
        for (int g = 0; g < 2; g++) {
            int idx = tid + g * 256;
            int d = idx >> 2, seg = idx & 3;
            cpa16(sb + OFF_B + (uint32_t)(s * TILEB + d * PITCHB + seg * 16), fsrc + idx * 16);
        }
        CP_COMMIT();
    }
    __syncthreads();   // skp visible

    {
        float4 j0p = jp[jj], j1p = jp[jj + 1];
        #pragma unroll
        for (int g = 0; g < 8; g++) {
            int i = ib + g * 16;
            float4 kp = skp[i];
            uint32_t w = g_bits[(size_t)(i0 + i) * 64];
            float z0 = kp.x + j0p.x;
            float m0 = (z0 > 0.f) ? kp.y * j0p.y : kp.z * j0p.z;
            float p0 = ((w >> jj) & 1u) ? m0 : j0p.w;
            float z1 = kp.x + j1p.x;
            float m1 = (z1 > 0.f) ? kp.y * j1p.y : kp.z * j1p.z;
            float p1 = ((w >> (jj + 1)) & 1u) ? m1 : j1p.w;
            *(uint32_t*)(smd + i * PITCHB + jj * 2) = pack2h(p0, p1);
        }
        CP_WAIT1();     // B0 complete (B1 may remain in flight)
        __syncthreads();
    }

    for (int c = 0; c < 64; c++) {
        const uint32_t aCur = sb + (uint32_t)((c & 1) * TILEB);
        const uint32_t bCur = sb + OFF_B + (uint32_t)((c % 3) * TILEB);
        const uint32_t nxa  = (uint32_t)(((c + 1) & 1) * TILEB);
        const bool issueB = (c <= 61);
        const bool pf = (c < 63);
        const int j0n = (c + 1) * 32;

        float4 j0p, j1p;
        uint32_t bw[8];
        if (issueB) {
            const uint8_t* fsrc = (const uint8_t*)(Fb + (size_t)(c + 2) * 4096);
            const uint32_t bdst = sb + OFF_B + (uint32_t)(((c + 2) % 3) * TILEB);
            #pragma unroll
            for (int g = 0; g < 2; g++) {
                int idx = tid + g * 256;
                int d = idx >> 2, seg = idx & 3;
                cpa16(bdst + (uint32_t)(d * PITCHB + seg * 16), fsrc + idx * 16);
            }
            CP_COMMIT();
        }
        if (pf) {
            j0p = jp[j0n + jj];
            j1p = jp[j0n + jj + 1];
            #pragma unroll
            for (int g = 0; g < 8; g++)
                bw[g] = g_bits[(size_t)(i0 + ib + g * 16) * 64 + (j0n >> 5)];
        }

        // MMA on current stage (128 rows); B(c) is complete
        mma_chunk1<4>(acc, aCur, bCur, wr, wc, lane);

        // compute + store next A
        if (pf) {
            #pragma unroll
            for (int g = 0; g < 8; g++) {
                int i = ib + g * 16;
                float4 kp = skp[i];
                float z0 = kp.x + j0p.x;
                float m0 = (z0 > 0.f) ? kp.y * j0p.y : kp.z * j0p.z;
                float p0 = ((bw[g] >> jj) & 1u) ? m0 : j0p.w;
                float z1 = kp.x + j1p.x;
                float m1 = (z1 > 0.f) ? kp.y * j1p.y : kp.z * j1p.z;
                float p1 = ((bw[g] >> (jj + 1)) & 1u) ? m1 : j1p.w;
                *(uint32_t*)(smd + nxa + i * PITCHB + jj * 2) = pack2h(p0, p1);
            }
        }
        if (issueB) { CP_WAIT1(); } else { CP_WAIT0(); }
        __syncthreads();
    }

    // epilogue
    #pragma unroll
    for (int it = 0; it < 4; it++) {
        int r = i0 + wr * 64 + it * 16 + (lane >> 2);
        #pragma unroll
        for (int nt = 0; nt < 4; nt++) {
            int c = wc * 32 + nt * 8 + (lane & 3) * 2;
            float* a = acc[it * 4 + nt];
            *(float2*)(out + ((size_t)b * NN + r) * DD + c)     = make_float2(a[0], a[1]);
            *(float2*)(out + ((size_t)b * NN + r + 8) * DD + c) = make_float2(a[2], a[3]);
        }
    }
}

// ---------------------------------------------------------------------------
extern "C" void kernel_launch(void* const* d_in, const int* in_sizes, int n_in,
                              void* d_out, int out_size)
{
    (void)in_sizes; (void)n_in; (void)out_size;
    const float* x     = (const float*)d_in[0];
    const float* adj   = (const float*)d_in[1];
    const float* W_emb = (const float*)d_in[2];
    const float* b_emb = (const float*)d_in[3];
    const float* w_q   = (const float*)d_in[4];
    const float* b_q   = (const float*)d_in[5];
    const float* w_k   = (const float*)d_in[6];
    const float* b_k   = (const float*)d_in[7];
    float* out = (float*)d_out;

    static bool attr_set = false;
    if (!attr_set) {
        cudaFuncSetAttribute(k_attn, cudaFuncAttributeMaxDynamicSharedMemorySize, SMEM_ATTN);
        attr_set = true;
    }

    k_prep2<<<512, 256>>>(adj);
    k_emb<<<(BB * NN) / 128, 256>>>(x, W_emb, b_emb, w_q, b_q, w_k, b_k);
    k_denom<<<dim3(NN / 128, BB, 8), 128>>>();
    k_attn<<<dim3(NN / 128, BB), 256, SMEM_ATTN>>>(out);
}